// round 12
// baseline (speedup 1.0000x reference)
#include <cuda_runtime.h>
#include <cuda_bf16.h>
#include <cstdint>

// NARX RNN, D=4, HID=64, NX=16, NT=512, NGRID=2048, NY=1.
//
// R12: Z scratch stored in MMA-FRAGMENT layout (both kernels share the same
// warp/lane fragment mapping over the same 128-g block), so Z moves as
// perfectly coalesced float4 streams: 16 STG.128 / 16 LDG.128 per thread
// instead of 64 scattered 32-bit accesses.  B-operand ldmatrix count halved
// via x4 n-tile pairing (lanes 16-31 address the +8-row tile).
//  1) uz_tc  : U = relu(x·W_in+b_in) (SIMT, bf16 split to smem);
//              Z = [U_hi|U_hi|U_lo]x[Wxh_hi|Wxh_lo|Wxh_hi] + b_h -> g_Z frags.
//  2) narx_tc: 3x  h = tanh(Zfrag + h·W_hh) via mma split; folded W_out.

typedef unsigned long long u64;

#define NT   512
#define NG   2048
#define NXF  16
#define DLY  4

// fragment layout: [tau][gblk(16)][tid(128)][16 float4]
__device__ float4 g_Z[(size_t)NT * 16 * 128 * 16];   // 268 MB

// ---------------- f32x2 helpers ----------------
__device__ __forceinline__ u64 fma2(u64 a, u64 b, u64 c) {
    u64 d; asm("fma.rn.f32x2 %0, %1, %2, %3;" : "=l"(d) : "l"(a), "l"(b), "l"(c));
    return d;
}
__device__ __forceinline__ u64 pack2(float x) {
    u64 r; asm("mov.b64 %0, {%1, %1};" : "=l"(r) : "f"(x));
    return r;
}
__device__ __forceinline__ u64 pack2b(float a, float b) {
    u64 r; asm("mov.b64 %0, {%1, %2};" : "=l"(r) : "f"(a), "f"(b));
    return r;
}
__device__ __forceinline__ void unpack2(u64 v, float& lo, float& hi) {
    asm("mov.b64 {%0, %1}, %2;" : "=f"(lo), "=f"(hi) : "l"(v));
}
__device__ __forceinline__ float tanh_fast(float v) {
    float e = __expf(2.0f * v);
    return 1.0f - __fdividef(2.0f, e + 1.0f);
}

// ---------------- mma.sync / ldmatrix wrappers ----------------
__device__ __forceinline__ uint32_t s2u(const void* p) {
    uint32_t a;
    asm("{ .reg .u64 t; cvta.to.shared.u64 t, %1; cvt.u32.u64 %0, t; }" : "=r"(a) : "l"(p));
    return a;
}
__device__ __forceinline__ void ldsm_x4(uint32_t& r0, uint32_t& r1,
                                        uint32_t& r2, uint32_t& r3, uint32_t a) {
    asm volatile("ldmatrix.sync.aligned.m8n8.x4.shared.b16 {%0,%1,%2,%3}, [%4];"
                 : "=r"(r0), "=r"(r1), "=r"(r2), "=r"(r3) : "r"(a));
}
__device__ __forceinline__ void mma_bf16(float* d, const uint32_t* a,
                                         uint32_t b0, uint32_t b1) {
    asm volatile("mma.sync.aligned.m16n8k16.row.col.f32.bf16.bf16.f32 "
                 "{%0,%1,%2,%3}, {%4,%5,%6,%7}, {%8,%9}, {%0,%1,%2,%3};"
                 : "+f"(d[0]), "+f"(d[1]), "+f"(d[2]), "+f"(d[3])
                 : "r"(a[0]), "r"(a[1]), "r"(a[2]), "r"(a[3]), "r"(b0), "r"(b1));
}
__device__ __forceinline__ uint32_t bfpack(float e, float o) {
    uint32_t r;
    asm("cvt.rn.bf16x2.f32 %0, %1, %2;" : "=r"(r) : "f"(o), "f"(e));
    return r;
}

#define HP 72     // padded A/H row (bf16)
#define BP 136    // padded B row (bf16): [hi(64) | lo(64) | pad]

// shared MMA fragment block: 3 split-terms over [A_hi|A_lo] x [B_hi|B_lo]
// (B ldmatrix x4 pairs n-tiles; bB0x4 lane-16+ offset is +8 rows)
#define MMA_STEP(aHi0, aLo0, bB0x4, dacc)                                     \
    _Pragma("unroll")                                                         \
    for (int kt = 0; kt < 4; kt++) {                                          \
        uint32_t ahi[2][4], alo[2][4];                                        \
        _Pragma("unroll")                                                     \
        for (int mt = 0; mt < 2; mt++) {                                      \
            const uint32_t moff = (mt * 16 * HP + kt * 16) * 2;               \
            ldsm_x4(ahi[mt][0], ahi[mt][1], ahi[mt][2], ahi[mt][3], (aHi0) + moff); \
            ldsm_x4(alo[mt][0], alo[mt][1], alo[mt][2], alo[mt][3], (aLo0) + moff); \
        }                                                                     \
        _Pragma("unroll")                                                     \
        for (int n2 = 0; n2 < 4; n2++) {                                      \
            uint32_t h0, h1, h2, h3, l0, l1, l2, l3;                          \
            ldsm_x4(h0, h1, h2, h3, (bB0x4) + (n2 * 16 * BP + kt * 16) * 2);  \
            ldsm_x4(l0, l1, l2, l3, (bB0x4) + (n2 * 16 * BP + 64 + kt * 16) * 2); \
            _Pragma("unroll")                                                 \
            for (int mt = 0; mt < 2; mt++) {                                  \
                mma_bf16(dacc[mt][2*n2],   ahi[mt], h0, h1);                  \
                mma_bf16(dacc[mt][2*n2],   ahi[mt], l0, l1);                  \
                mma_bf16(dacc[mt][2*n2],   alo[mt], h0, h1);                  \
                mma_bf16(dacc[mt][2*n2+1], ahi[mt], h2, h3);                  \
                mma_bf16(dacc[mt][2*n2+1], ahi[mt], l2, l3);                  \
                mma_bf16(dacc[mt][2*n2+1], alo[mt], h2, h3);                  \
            }                                                                 \
        }                                                                     \
    }

// ================= kernel 1: uz_tc =================
#define UZ_OFF_ULO 18432
#define UZ_OFF_B   36864
#define UZ_OFF_BH  54272
#define UZ_OFF_WIN 54528
#define UZ_OFF_BIN 62720
#define UZ_SMEM    63232

__global__ __launch_bounds__(128)
void uz_tc(const float* __restrict__ x,
           const float* __restrict__ W_in, const float* __restrict__ b_in,
           const float* __restrict__ W_xh, const float* __restrict__ b_h,
           float* __restrict__ out)
{
    extern __shared__ char sm[];
    const uint32_t sbase = s2u(sm);
    __nv_bfloat16* Bm  = (__nv_bfloat16*)(sm + UZ_OFF_B);
    float* sBh   = (float*)(sm + UZ_OFF_BH);
    u64*   sWin2 = (u64*)(sm + UZ_OFF_WIN);
    u64*   sBin2 = (u64*)(sm + UZ_OFF_BIN);

    const int tid  = threadIdx.x;
    const int lane = tid & 31;
    const int wrp  = tid >> 5;

    for (int i = tid; i < NXF * 64; i += 128) sWin2[i] = pack2(W_in[i]);
    for (int idx = tid; idx < 4096; idx += 128) {
        const int k = idx >> 6, j = idx & 63;
        const float w = W_xh[idx];
        const __nv_bfloat16 hb = __float2bfloat16(w);
        const __nv_bfloat16 lb = __float2bfloat16(w - __bfloat162float(hb));
        Bm[j * BP + k]      = hb;
        Bm[j * BP + 64 + k] = lb;
    }
    if (tid < 64) { sBin2[tid] = pack2(b_in[tid]); sBh[tid] = b_h[tid]; }

    const int b    = blockIdx.x;          // 512 * 16
    const int tau  = b >> 4;
    const int gblk = b & 15;
    const int g0   = gblk << 7;

    if (tau < DLY && tid < 64) {
        const float2 z0 = {0.0f, 0.0f};
        *(float2*)(out + (size_t)tau * NG + g0 + 2 * tid) = z0;
    }

    // ---- phase A: U = relu(x·W_in + b_in), bf16 hi/lo into smem ----
    {
        const int unit = tid >> 1;
        const int kh   = tid & 1;
        const int re   = 2 * unit, ro = re + 1;

        const float4* xr = (const float4*)(x + ((size_t)tau * NG + g0 + re) * NXF);
        float4 r0[4] = { xr[0], xr[1], xr[2], xr[3] };
        float4 r1[4] = { xr[4], xr[5], xr[6], xr[7] };
        const float* fa = (const float*)r0;
        const float* fb = (const float*)r1;
        u64 x2[16];
        #pragma unroll
        for (int i = 0; i < 16; i++) x2[i] = pack2b(fa[i], fb[i]);

        __syncthreads();

        __nv_bfloat16* Uhi = (__nv_bfloat16*)sm;
        __nv_bfloat16* Ulo = (__nv_bfloat16*)(sm + UZ_OFF_ULO);

        #pragma unroll 4
        for (int kk = 0; kk < 16; kk++) {
            const int k = kh * 32 + 2 * kk;
            u64 u0 = sBin2[k], u1 = sBin2[k + 1];
            #pragma unroll
            for (int i = 0; i < 16; i++) {
                u0 = fma2(x2[i], sWin2[i * 64 + k],     u0);
                u1 = fma2(x2[i], sWin2[i * 64 + k + 1], u1);
            }
            float e0, o0, e1, o1;
            unpack2(u0, e0, o0); unpack2(u1, e1, o1);
            e0 = fmaxf(e0, 0.0f); o0 = fmaxf(o0, 0.0f);
            e1 = fmaxf(e1, 0.0f); o1 = fmaxf(o1, 0.0f);

            const uint32_t pE = bfpack(e0, e1);
            const uint32_t pO = bfpack(o0, o1);
            const float fE0 = __uint_as_float(pE << 16);
            const float fE1 = __uint_as_float(pE & 0xFFFF0000u);
            const float fO0 = __uint_as_float(pO << 16);
            const float fO1 = __uint_as_float(pO & 0xFFFF0000u);
            const uint32_t qE = bfpack(e0 - fE0, e1 - fE1);
            const uint32_t qO = bfpack(o0 - fO0, o1 - fO1);

            *(uint32_t*)(Uhi + re * HP + k) = pE;
            *(uint32_t*)(Uhi + ro * HP + k) = pO;
            *(uint32_t*)(Ulo + re * HP + k) = qE;
            *(uint32_t*)(Ulo + ro * HP + k) = qO;
        }
    }
    __syncthreads();

    // ---- phase B: mma -> Z fragments ----
    const int aRow = (lane & 7) + ((lane >> 3) & 1) * 8;
    const int aCol = (lane >> 4) << 3;
    const int bRow = lane & 7;
    const int bCol = ((lane >> 3) & 1) * 8;
    const int m0w  = wrp << 5;
    const uint32_t aHi0  = sbase +              ((m0w + aRow) * HP + aCol) * 2;
    const uint32_t aLo0  = sbase + UZ_OFF_ULO + ((m0w + aRow) * HP + aCol) * 2;
    const uint32_t bB0x4 = sbase + UZ_OFF_B +
                           ((bRow + (lane >> 4) * 8) * BP + bCol) * 2;

    const int qc = (lane & 3) << 1;

    float dacc[2][8][4];
    #pragma unroll
    for (int mt = 0; mt < 2; mt++)
        #pragma unroll
        for (int n = 0; n < 8; n++)
            #pragma unroll
            for (int q = 0; q < 4; q++) dacc[mt][n][q] = 0.0f;

    MMA_STEP(aHi0, aLo0, bB0x4, dacc)

    float4* Zv = g_Z + (((size_t)tau * 16 + gblk) * 128 + tid) * 16;
    #pragma unroll
    for (int mt = 0; mt < 2; mt++) {
        #pragma unroll
        for (int n = 0; n < 8; n++) {
            const int c0 = (n << 3) + qc;
            const float b0 = sBh[c0], b1 = sBh[c0 + 1];
            float4 v;
            v.x = dacc[mt][n][0] + b0;
            v.y = dacc[mt][n][1] + b1;
            v.z = dacc[mt][n][2] + b0;
            v.w = dacc[mt][n][3] + b1;
            Zv[mt * 8 + n] = v;
        }
    }
}

// ================= kernel 2: narx_tc =================
#define OFF_HLO 18432
#define OFF_B   36864
#define OFF_WO  54272
#define OFF_BO  54528
#define TC_SMEM 54784

__global__ __launch_bounds__(128)
void narx_tc(const float* __restrict__ W_hh, const float* __restrict__ W_out,
             const float* __restrict__ b_out, float* __restrict__ out)
{
    extern __shared__ char sm[];
    const uint32_t sbase = s2u(sm);
    __nv_bfloat16* Bm  = (__nv_bfloat16*)(sm + OFF_B);
    float* sWo = (float*)(sm + OFF_WO);
    float* sBo = (float*)(sm + OFF_BO);

    const int tid  = threadIdx.x;
    const int lane = tid & 31;
    const int wrp  = tid >> 5;

    for (int idx = tid; idx < 4096; idx += 128) {
        const int k = idx >> 6, j = idx & 63;
        const float w = W_hh[idx];
        const __nv_bfloat16 hb = __float2bfloat16(w);
        const __nv_bfloat16 lb = __float2bfloat16(w - __bfloat162float(hb));
        Bm[j * BP + k]      = hb;
        Bm[j * BP + 64 + k] = lb;
    }
    if (tid < 64) sWo[tid] = W_out[tid];
    if (tid == 0) sBo[0] = b_out[0];
    __syncthreads();

    const int b    = blockIdx.x;                 // 508*16
    const int t    = DLY + (b >> 4);
    const int gblk = b & 15;
    const int g0   = gblk << 7;

    const int aRow = (lane & 7) + ((lane >> 3) & 1) * 8;
    const int aCol = (lane >> 4) << 3;
    const int bRow = lane & 7;
    const int bCol = ((lane >> 3) & 1) * 8;
    const int m0w  = wrp << 5;
    const uint32_t aHi0  = sbase +           ((m0w + aRow) * HP + aCol) * 2;
    const uint32_t aLo0  = sbase + OFF_HLO + ((m0w + aRow) * HP + aCol) * 2;
    const uint32_t bB0x4 = sbase + OFF_B +
                           ((bRow + (lane >> 4) * 8) * BP + bCol) * 2;

    const int qr = lane >> 2;
    const int qc = (lane & 3) << 1;

    float dacc[2][8][4];
    float yacc[2][2] = {{0.f, 0.f}, {0.f, 0.f}};

    for (int d = 0; d < 4; d++) {
        const int tau = t - DLY + d;
        const float4* Zv = g_Z + (((size_t)tau * 16 + gblk) * 128 + tid) * 16;

        #pragma unroll
        for (int mt = 0; mt < 2; mt++)
            #pragma unroll
            for (int n = 0; n < 8; n++)
                #pragma unroll
                for (int q = 0; q < 4; q++) dacc[mt][n][q] = 0.0f;

        if (d > 0) {
            MMA_STEP(aHi0, aLo0, bB0x4, dacc)
        }

        __syncwarp();

        #pragma unroll
        for (int mt = 0; mt < 2; mt++) {
            const int r0 = m0w + mt * 16 + qr;
            #pragma unroll
            for (int n = 0; n < 8; n++) {
                const int c0 = (n << 3) + qc;
                const float4 zv = Zv[mt * 8 + n];

                const float h00 = tanh_fast(dacc[mt][n][0] + zv.x);
                const float h01 = tanh_fast(dacc[mt][n][1] + zv.y);
                const float h10 = tanh_fast(dacc[mt][n][2] + zv.z);
                const float h11 = tanh_fast(dacc[mt][n][3] + zv.w);

                if (d < 3) {
                    const uint32_t p0 = bfpack(h00, h01);
                    const uint32_t p1 = bfpack(h10, h11);
                    const float f00 = __uint_as_float(p0 << 16);
                    const float f01 = __uint_as_float(p0 & 0xFFFF0000u);
                    const float f10 = __uint_as_float(p1 << 16);
                    const float f11 = __uint_as_float(p1 & 0xFFFF0000u);
                    const uint32_t q0 = bfpack(h00 - f00, h01 - f01);
                    const uint32_t q1 = bfpack(h10 - f10, h11 - f11);
                    const int o0 = (r0 * HP + c0) * 2;
                    const int o1 = ((r0 + 8) * HP + c0) * 2;
                    *(uint32_t*)(sm + o0)           = p0;
                    *(uint32_t*)(sm + o1)           = p1;
                    *(uint32_t*)(sm + OFF_HLO + o0) = q0;
                    *(uint32_t*)(sm + OFF_HLO + o1) = q1;
                } else {
                    const float w0 = sWo[c0], w1 = sWo[c0 + 1];
                    yacc[mt][0] += h00 * w0 + h01 * w1;
                    yacc[mt][1] += h10 * w0 + h11 * w1;
                }
            }
        }
        __syncwarp();
    }

    const float bo = sBo[0];
    #pragma unroll
    for (int mt = 0; mt < 2; mt++)
        #pragma unroll
        for (int hf = 0; hf < 2; hf++) {
            float v = yacc[mt][hf];
            v += __shfl_xor_sync(0xFFFFFFFFu, v, 1);
            v += __shfl_xor_sync(0xFFFFFFFFu, v, 2);
            if ((lane & 3) == 0) {
                const int row = m0w + mt * 16 + qr + hf * 8;
                out[(size_t)t * NG + g0 + row] = v + bo;
            }
        }
}

extern "C" void kernel_launch(void* const* d_in, const int* in_sizes, int n_in,
                              void* d_out, int out_size) {
    const float* x     = (const float*)d_in[0];
    const float* W_in  = (const float*)d_in[1];
    const float* b_in  = (const float*)d_in[2];
    const float* W_xh  = (const float*)d_in[3];
    const float* W_hh  = (const float*)d_in[4];
    const float* b_h   = (const float*)d_in[5];
    const float* W_out = (const float*)d_in[6];
    const float* b_out = (const float*)d_in[7];
    float* out = (float*)d_out;

    cudaFuncSetAttribute(uz_tc, cudaFuncAttributeMaxDynamicSharedMemorySize,
                         UZ_SMEM);
    cudaFuncSetAttribute(narx_tc, cudaFuncAttributeMaxDynamicSharedMemorySize,
                         TC_SMEM);

    uz_tc<<<NT * 16, 128, UZ_SMEM>>>(x, W_in, b_in, W_xh, b_h, out);
    narx_tc<<<(NT - DLY) * 16, 128, TC_SMEM>>>(W_hh, W_out, b_out, out);
    (void)in_sizes; (void)n_in; (void)out_size;
}

// round 15
// speedup vs baseline: 1.3527x; 1.3527x over previous
#include <cuda_runtime.h>
#include <cuda_bf16.h>
#include <cstdint>

// NARX RNN, D=4, HID=64, NX=16, NT=512, NGRID=2048, NY=1.
//
// R14 = R13 resubmit (infra failed; design untested).
// Z scratch in MMA-fragment layout, COALESCED order:
//   g_Z index = [tau][gblk(16)][frag(16)][tid(128)] float4  (lane stride 16 B)
// (R12's regression was [tid][frag]: lane stride 256 B -> 32 lines/LDG.128.)
//  1) uz_tc  : U = relu(x·W_in+b_in) (SIMT, bf16 split to smem);
//              Z = [U_hi|U_hi|U_lo]x[Wxh_hi|Wxh_lo|Wxh_hi] + b_h -> g_Z frags.
//  2) narx_tc: 3x  h = tanh(Zfrag + h·W_hh) via mma split; folded W_out.

typedef unsigned long long u64;

#define NT   512
#define NG   2048
#define NXF  16
#define DLY  4

// fragment layout: [tau][gblk(16)][frag(16)][tid(128)] float4
__device__ float4 g_Z[(size_t)NT * 16 * 16 * 128];   // 268 MB

// ---------------- f32x2 helpers ----------------
__device__ __forceinline__ u64 fma2(u64 a, u64 b, u64 c) {
    u64 d; asm("fma.rn.f32x2 %0, %1, %2, %3;" : "=l"(d) : "l"(a), "l"(b), "l"(c));
    return d;
}
__device__ __forceinline__ u64 pack2(float x) {
    u64 r; asm("mov.b64 %0, {%1, %1};" : "=l"(r) : "f"(x));
    return r;
}
__device__ __forceinline__ u64 pack2b(float a, float b) {
    u64 r; asm("mov.b64 %0, {%1, %2};" : "=l"(r) : "f"(a), "f"(b));
    return r;
}
__device__ __forceinline__ void unpack2(u64 v, float& lo, float& hi) {
    asm("mov.b64 {%0, %1}, %2;" : "=f"(lo), "=f"(hi) : "l"(v));
}
__device__ __forceinline__ float tanh_fast(float v) {
    float e = __expf(2.0f * v);
    return 1.0f - __fdividef(2.0f, e + 1.0f);
}

// ---------------- mma.sync / ldmatrix wrappers ----------------
__device__ __forceinline__ uint32_t s2u(const void* p) {
    uint32_t a;
    asm("{ .reg .u64 t; cvta.to.shared.u64 t, %1; cvt.u32.u64 %0, t; }" : "=r"(a) : "l"(p));
    return a;
}
__device__ __forceinline__ void ldsm_x4(uint32_t& r0, uint32_t& r1,
                                        uint32_t& r2, uint32_t& r3, uint32_t a) {
    asm volatile("ldmatrix.sync.aligned.m8n8.x4.shared.b16 {%0,%1,%2,%3}, [%4];"
                 : "=r"(r0), "=r"(r1), "=r"(r2), "=r"(r3) : "r"(a));
}
__device__ __forceinline__ void mma_bf16(float* d, const uint32_t* a,
                                         uint32_t b0, uint32_t b1) {
    asm volatile("mma.sync.aligned.m16n8k16.row.col.f32.bf16.bf16.f32 "
                 "{%0,%1,%2,%3}, {%4,%5,%6,%7}, {%8,%9}, {%0,%1,%2,%3};"
                 : "+f"(d[0]), "+f"(d[1]), "+f"(d[2]), "+f"(d[3])
                 : "r"(a[0]), "r"(a[1]), "r"(a[2]), "r"(a[3]), "r"(b0), "r"(b1));
}
__device__ __forceinline__ uint32_t bfpack(float e, float o) {
    uint32_t r;
    asm("cvt.rn.bf16x2.f32 %0, %1, %2;" : "=r"(r) : "f"(o), "f"(e));
    return r;
}

#define HP 72     // padded A/H row (bf16)
#define BP 136    // padded B row (bf16): [hi(64) | lo(64) | pad]

// shared MMA fragment block: 3 split-terms over [A_hi|A_lo] x [B_hi|B_lo]
// (B ldmatrix x4 pairs n-tiles; bB0x4 lanes 16-31 address the +8-row tile)
#define MMA_STEP(aHi0, aLo0, bB0x4, dacc)                                     \
    _Pragma("unroll")                                                         \
    for (int kt = 0; kt < 4; kt++) {                                          \
        uint32_t ahi[2][4], alo[2][4];                                        \
        _Pragma("unroll")                                                     \
        for (int mt = 0; mt < 2; mt++) {                                      \
            const uint32_t moff = (mt * 16 * HP + kt * 16) * 2;               \
            ldsm_x4(ahi[mt][0], ahi[mt][1], ahi[mt][2], ahi[mt][3], (aHi0) + moff); \
            ldsm_x4(alo[mt][0], alo[mt][1], alo[mt][2], alo[mt][3], (aLo0) + moff); \
        }                                                                     \
        _Pragma("unroll")                                                     \
        for (int n2 = 0; n2 < 4; n2++) {                                      \
            uint32_t h0, h1, h2, h3, l0, l1, l2, l3;                          \
            ldsm_x4(h0, h1, h2, h3, (bB0x4) + (n2 * 16 * BP + kt * 16) * 2);  \
            ldsm_x4(l0, l1, l2, l3, (bB0x4) + (n2 * 16 * BP + 64 + kt * 16) * 2); \
            _Pragma("unroll")                                                 \
            for (int mt = 0; mt < 2; mt++) {                                  \
                mma_bf16(dacc[mt][2*n2],   ahi[mt], h0, h1);                  \
                mma_bf16(dacc[mt][2*n2],   ahi[mt], l0, l1);                  \
                mma_bf16(dacc[mt][2*n2],   alo[mt], h0, h1);                  \
                mma_bf16(dacc[mt][2*n2+1], ahi[mt], h2, h3);                  \
                mma_bf16(dacc[mt][2*n2+1], ahi[mt], l2, l3);                  \
                mma_bf16(dacc[mt][2*n2+1], alo[mt], h2, h3);                  \
            }                                                                 \
        }                                                                     \
    }

// ================= kernel 1: uz_tc =================
#define UZ_OFF_ULO 18432
#define UZ_OFF_B   36864
#define UZ_OFF_BH  54272
#define UZ_OFF_WIN 54528
#define UZ_OFF_BIN 62720
#define UZ_SMEM    63232

__global__ __launch_bounds__(128)
void uz_tc(const float* __restrict__ x,
           const float* __restrict__ W_in, const float* __restrict__ b_in,
           const float* __restrict__ W_xh, const float* __restrict__ b_h,
           float* __restrict__ out)
{
    extern __shared__ char sm[];
    const uint32_t sbase = s2u(sm);
    __nv_bfloat16* Bm  = (__nv_bfloat16*)(sm + UZ_OFF_B);
    float* sBh   = (float*)(sm + UZ_OFF_BH);
    u64*   sWin2 = (u64*)(sm + UZ_OFF_WIN);
    u64*   sBin2 = (u64*)(sm + UZ_OFF_BIN);

    const int tid  = threadIdx.x;
    const int lane = tid & 31;
    const int wrp  = tid >> 5;

    for (int i = tid; i < NXF * 64; i += 128) sWin2[i] = pack2(W_in[i]);
    for (int idx = tid; idx < 4096; idx += 128) {
        const int k = idx >> 6, j = idx & 63;
        const float w = W_xh[idx];
        const __nv_bfloat16 hb = __float2bfloat16(w);
        const __nv_bfloat16 lb = __float2bfloat16(w - __bfloat162float(hb));
        Bm[j * BP + k]      = hb;
        Bm[j * BP + 64 + k] = lb;
    }
    if (tid < 64) { sBin2[tid] = pack2(b_in[tid]); sBh[tid] = b_h[tid]; }

    const int b    = blockIdx.x;          // 512 * 16
    const int tau  = b >> 4;
    const int gblk = b & 15;
    const int g0   = gblk << 7;

    if (tau < DLY && tid < 64) {
        const float2 z0 = {0.0f, 0.0f};
        *(float2*)(out + (size_t)tau * NG + g0 + 2 * tid) = z0;
    }

    // ---- phase A: U = relu(x·W_in + b_in), bf16 hi/lo into smem ----
    {
        const int unit = tid >> 1;
        const int kh   = tid & 1;
        const int re   = 2 * unit, ro = re + 1;

        const float4* xr = (const float4*)(x + ((size_t)tau * NG + g0 + re) * NXF);
        float4 r0[4] = { xr[0], xr[1], xr[2], xr[3] };
        float4 r1[4] = { xr[4], xr[5], xr[6], xr[7] };
        const float* fa = (const float*)r0;
        const float* fb = (const float*)r1;
        u64 x2[16];
        #pragma unroll
        for (int i = 0; i < 16; i++) x2[i] = pack2b(fa[i], fb[i]);

        __syncthreads();

        __nv_bfloat16* Uhi = (__nv_bfloat16*)sm;
        __nv_bfloat16* Ulo = (__nv_bfloat16*)(sm + UZ_OFF_ULO);

        #pragma unroll 4
        for (int kk = 0; kk < 16; kk++) {
            const int k = kh * 32 + 2 * kk;
            u64 u0 = sBin2[k], u1 = sBin2[k + 1];
            #pragma unroll
            for (int i = 0; i < 16; i++) {
                u0 = fma2(x2[i], sWin2[i * 64 + k],     u0);
                u1 = fma2(x2[i], sWin2[i * 64 + k + 1], u1);
            }
            float e0, o0, e1, o1;
            unpack2(u0, e0, o0); unpack2(u1, e1, o1);
            e0 = fmaxf(e0, 0.0f); o0 = fmaxf(o0, 0.0f);
            e1 = fmaxf(e1, 0.0f); o1 = fmaxf(o1, 0.0f);

            const uint32_t pE = bfpack(e0, e1);
            const uint32_t pO = bfpack(o0, o1);
            const float fE0 = __uint_as_float(pE << 16);
            const float fE1 = __uint_as_float(pE & 0xFFFF0000u);
            const float fO0 = __uint_as_float(pO << 16);
            const float fO1 = __uint_as_float(pO & 0xFFFF0000u);
            const uint32_t qE = bfpack(e0 - fE0, e1 - fE1);
            const uint32_t qO = bfpack(o0 - fO0, o1 - fO1);

            *(uint32_t*)(Uhi + re * HP + k) = pE;
            *(uint32_t*)(Uhi + ro * HP + k) = pO;
            *(uint32_t*)(Ulo + re * HP + k) = qE;
            *(uint32_t*)(Ulo + ro * HP + k) = qO;
        }
    }
    __syncthreads();

    // ---- phase B: mma -> Z fragments ----
    const int aRow = (lane & 7) + ((lane >> 3) & 1) * 8;
    const int aCol = (lane >> 4) << 3;
    const int bRow = lane & 7;
    const int bCol = ((lane >> 3) & 1) * 8;
    const int m0w  = wrp << 5;
    const uint32_t aHi0  = sbase +              ((m0w + aRow) * HP + aCol) * 2;
    const uint32_t aLo0  = sbase + UZ_OFF_ULO + ((m0w + aRow) * HP + aCol) * 2;
    const uint32_t bB0x4 = sbase + UZ_OFF_B +
                           ((bRow + (lane >> 4) * 8) * BP + bCol) * 2;

    const int qc = (lane & 3) << 1;

    float dacc[2][8][4];
    #pragma unroll
    for (int mt = 0; mt < 2; mt++)
        #pragma unroll
        for (int n = 0; n < 8; n++)
            #pragma unroll
            for (int q = 0; q < 4; q++) dacc[mt][n][q] = 0.0f;

    MMA_STEP(aHi0, aLo0, bB0x4, dacc)

    // coalesced store: frag-major, tid contiguous
    float4* Zv = g_Z + ((size_t)tau * 16 + gblk) * 16 * 128 + tid;
    #pragma unroll
    for (int mt = 0; mt < 2; mt++) {
        #pragma unroll
        for (int n = 0; n < 8; n++) {
            const int c0 = (n << 3) + qc;
            const float b0 = sBh[c0], b1 = sBh[c0 + 1];
            float4 v;
            v.x = dacc[mt][n][0] + b0;
            v.y = dacc[mt][n][1] + b1;
            v.z = dacc[mt][n][2] + b0;
            v.w = dacc[mt][n][3] + b1;
            Zv[(mt * 8 + n) * 128] = v;
        }
    }
}

// ================= kernel 2: narx_tc =================
#define OFF_HLO 18432
#define OFF_B   36864
#define OFF_WO  54272
#define OFF_BO  54528
#define TC_SMEM 54784

__global__ __launch_bounds__(128)
void narx_tc(const float* __restrict__ W_hh, const float* __restrict__ W_out,
             const float* __restrict__ b_out, float* __restrict__ out)
{
    extern __shared__ char sm[];
    const uint32_t sbase = s2u(sm);
    __nv_bfloat16* Bm  = (__nv_bfloat16*)(sm + OFF_B);
    float* sWo = (float*)(sm + OFF_WO);
    float* sBo = (float*)(sm + OFF_BO);

    const int tid  = threadIdx.x;
    const int lane = tid & 31;
    const int wrp  = tid >> 5;

    for (int idx = tid; idx < 4096; idx += 128) {
        const int k = idx >> 6, j = idx & 63;
        const float w = W_hh[idx];
        const __nv_bfloat16 hb = __float2bfloat16(w);
        const __nv_bfloat16 lb = __float2bfloat16(w - __bfloat162float(hb));
        Bm[j * BP + k]      = hb;
        Bm[j * BP + 64 + k] = lb;
    }
    if (tid < 64) sWo[tid] = W_out[tid];
    if (tid == 0) sBo[0] = b_out[0];
    __syncthreads();

    const int b    = blockIdx.x;                 // 508*16
    const int t    = DLY + (b >> 4);
    const int gblk = b & 15;
    const int g0   = gblk << 7;

    const int aRow = (lane & 7) + ((lane >> 3) & 1) * 8;
    const int aCol = (lane >> 4) << 3;
    const int bRow = lane & 7;
    const int bCol = ((lane >> 3) & 1) * 8;
    const int m0w  = wrp << 5;
    const uint32_t aHi0  = sbase +           ((m0w + aRow) * HP + aCol) * 2;
    const uint32_t aLo0  = sbase + OFF_HLO + ((m0w + aRow) * HP + aCol) * 2;
    const uint32_t bB0x4 = sbase + OFF_B +
                           ((bRow + (lane >> 4) * 8) * BP + bCol) * 2;

    const int qr = lane >> 2;
    const int qc = (lane & 3) << 1;

    float dacc[2][8][4];
    float yacc[2][2] = {{0.f, 0.f}, {0.f, 0.f}};

    for (int d = 0; d < 4; d++) {
        const int tau = t - DLY + d;
        const float4* Zv = g_Z + ((size_t)tau * 16 + gblk) * 16 * 128 + tid;

        #pragma unroll
        for (int mt = 0; mt < 2; mt++)
            #pragma unroll
            for (int n = 0; n < 8; n++)
                #pragma unroll
                for (int q = 0; q < 4; q++) dacc[mt][n][q] = 0.0f;

        if (d > 0) {
            MMA_STEP(aHi0, aLo0, bB0x4, dacc)
        }

        __syncwarp();

        #pragma unroll
        for (int mt = 0; mt < 2; mt++) {
            const int r0 = m0w + mt * 16 + qr;
            #pragma unroll
            for (int n = 0; n < 8; n++) {
                const int c0 = (n << 3) + qc;
                const float4 zv = Zv[(mt * 8 + n) * 128];

                const float h00 = tanh_fast(dacc[mt][n][0] + zv.x);
                const float h01 = tanh_fast(dacc[mt][n][1] + zv.y);
                const float h10 = tanh_fast(dacc[mt][n][2] + zv.z);
                const float h11 = tanh_fast(dacc[mt][n][3] + zv.w);

                if (d < 3) {
                    const uint32_t p0 = bfpack(h00, h01);
                    const uint32_t p1 = bfpack(h10, h11);
                    const float f00 = __uint_as_float(p0 << 16);
                    const float f01 = __uint_as_float(p0 & 0xFFFF0000u);
                    const float f10 = __uint_as_float(p1 << 16);
                    const float f11 = __uint_as_float(p1 & 0xFFFF0000u);
                    const uint32_t q0 = bfpack(h00 - f00, h01 - f01);
                    const uint32_t q1 = bfpack(h10 - f10, h11 - f11);
                    const int o0 = (r0 * HP + c0) * 2;
                    const int o1 = ((r0 + 8) * HP + c0) * 2;
                    *(uint32_t*)(sm + o0)           = p0;
                    *(uint32_t*)(sm + o1)           = p1;
                    *(uint32_t*)(sm + OFF_HLO + o0) = q0;
                    *(uint32_t*)(sm + OFF_HLO + o1) = q1;
                } else {
                    const float w0 = sWo[c0], w1 = sWo[c0 + 1];
                    yacc[mt][0] += h00 * w0 + h01 * w1;
                    yacc[mt][1] += h10 * w0 + h11 * w1;
                }
            }
        }
        __syncwarp();
    }

    const float bo = sBo[0];
    #pragma unroll
    for (int mt = 0; mt < 2; mt++)
        #pragma unroll
        for (int hf = 0; hf < 2; hf++) {
            float v = yacc[mt][hf];
            v += __shfl_xor_sync(0xFFFFFFFFu, v, 1);
            v += __shfl_xor_sync(0xFFFFFFFFu, v, 2);
            if ((lane & 3) == 0) {
                const int row = m0w + mt * 16 + qr + hf * 8;
                out[(size_t)t * NG + g0 + row] = v + bo;
            }
        }
}

extern "C" void kernel_launch(void* const* d_in, const int* in_sizes, int n_in,
                              void* d_out, int out_size) {
    const float* x     = (const float*)d_in[0];
    const float* W_in  = (const float*)d_in[1];
    const float* b_in  = (const float*)d_in[2];
    const float* W_xh  = (const float*)d_in[3];
    const float* W_hh  = (const float*)d_in[4];
    const float* b_h   = (const float*)d_in[5];
    const float* W_out = (const float*)d_in[6];
    const float* b_out = (const float*)d_in[7];
    float* out = (float*)d_out;

    cudaFuncSetAttribute(uz_tc, cudaFuncAttributeMaxDynamicSharedMemorySize,
                         UZ_SMEM);
    cudaFuncSetAttribute(narx_tc, cudaFuncAttributeMaxDynamicSharedMemorySize,
                         TC_SMEM);

    uz_tc<<<NT * 16, 128, UZ_SMEM>>>(x, W_in, b_in, W_xh, b_h, out);
    narx_tc<<<(NT - DLY) * 16, 128, TC_SMEM>>>(W_hh, W_out, b_out, out);
    (void)in_sizes; (void)n_in; (void)out_size;
}